// round 16
// baseline (speedup 1.0000x reference)
#include <cuda_runtime.h>
#include <cuda_bf16.h>
#include <cuda_fp16.h>
#include <cstdint>

#define BATCH 4
#define SEQ   2048
#define EMB   1024
#define NH    16
#define HD    64
#define TOK   (BATCH*SEQ)      // 8192

// ---------------- scratch (device globals; single fp16 everywhere) ---------
__device__ __nv_bfloat16 g_x16[(size_t)TOK * EMB];        // fp16
__device__ __nv_bfloat16 g_wq[(size_t)3 * EMB * EMB];     // fp16
__device__ __nv_bfloat16 g_wp[(size_t)EMB * EMB];         // fp16
__device__ __nv_bfloat16 g_qkv[(size_t)TOK * 3 * EMB];    // fp16 (Q scaled)
__device__ __nv_bfloat16 g_att[(size_t)TOK * EMB];        // fp16

// ---------------- primitives ----------------
__device__ __forceinline__ uint32_t smem_u32(const void* p) {
    uint32_t a;
    asm("{ .reg .u64 t; cvta.to.shared.u64 t, %1; cvt.u32.u64 %0, t; }" : "=r"(a) : "l"(p));
    return a;
}
__device__ __forceinline__ void ldm_x4(uint32_t* r, uint32_t addr) {
    asm volatile("ldmatrix.sync.aligned.m8n8.x4.shared.b16 {%0,%1,%2,%3}, [%4];"
        : "=r"(r[0]), "=r"(r[1]), "=r"(r[2]), "=r"(r[3]) : "r"(addr));
}
__device__ __forceinline__ void ldm_x4_t(uint32_t* r, uint32_t addr) {
    asm volatile("ldmatrix.sync.aligned.m8n8.x4.trans.shared.b16 {%0,%1,%2,%3}, [%4];"
        : "=r"(r[0]), "=r"(r[1]), "=r"(r[2]), "=r"(r[3]) : "r"(addr));
}
__device__ __forceinline__ void mma16816h(float* c, const uint32_t* a, const uint32_t* b) {
    asm volatile(
        "mma.sync.aligned.m16n8k16.row.col.f32.f16.f16.f32 "
        "{%0,%1,%2,%3}, {%4,%5,%6,%7}, {%8,%9}, {%0,%1,%2,%3};"
        : "+f"(c[0]), "+f"(c[1]), "+f"(c[2]), "+f"(c[3])
        : "r"(a[0]), "r"(a[1]), "r"(a[2]), "r"(a[3]), "r"(b[0]), "r"(b[1]));
}
// fp16-accumulate variant (D/C in 2 regs)
__device__ __forceinline__ void mma16816hh(uint32_t* d, const uint32_t* a, const uint32_t* b) {
    asm volatile(
        "mma.sync.aligned.m16n8k16.row.col.f16.f16.f16.f16 "
        "{%0,%1}, {%2,%3,%4,%5}, {%6,%7}, {%0,%1};"
        : "+r"(d[0]), "+r"(d[1])
        : "r"(a[0]), "r"(a[1]), "r"(a[2]), "r"(a[3]), "r"(b[0]), "r"(b[1]));
}
#define CP16(dst, src) \
    asm volatile("cp.async.cg.shared.global [%0], [%1], 16;" \
        :: "r"(dst), "l"(src) : "memory")
#define CP_COMMIT() asm volatile("cp.async.commit_group;" ::: "memory")
#define CP_WAIT0()  asm volatile("cp.async.wait_group 0;" ::: "memory")

__device__ __forceinline__ uint32_t pack_h2(float x, float y) {
    __half2 h = __floats2half2_rn(x, y);
    return *(uint32_t*)&h;
}

// ---------------- conversion kernel (fp32 -> fp16) ----------------
__global__ void __launch_bounds__(256)
cvt_f32h(const float* __restrict__ in, __nv_bfloat16* __restrict__ h, int n4)
{
    int i = blockIdx.x * blockDim.x + threadIdx.x;
    if (i < n4) {
        float4 v = ((const float4*)in)[i];
        uint2 hi;
        hi.x = pack_h2(v.x, v.y);
        hi.y = pack_h2(v.z, v.w);
        ((uint2*)h)[i] = hi;
    }
}

// ======== fp16 1-term GEMM: C = A16 x W16^T + bias (round-15, kept) ========
#define ROWB    80
#define PLANE_B (128 * ROWB)      // 10240
#define P_A     0
#define P_W     (1 * PLANE_B)
#define BUF_B   (2 * PLANE_B)     // 20480
#define GEMM_SMEM (2 * BUF_B)     // 40960

__device__ __forceinline__ void mma_block_h(float acc[2][8][4],
        const uint32_t a[2][4], const uint32_t b[4][4]) {
    #pragma unroll
    for (int mt = 0; mt < 2; mt++)
        #pragma unroll
        for (int p = 0; p < 4; p++) {
            uint32_t b0[2] = { b[p][0], b[p][2] };
            uint32_t b1[2] = { b[p][1], b[p][3] };
            mma16816h(acc[mt][2*p+0], a[mt], b0);
            mma16816h(acc[mt][2*p+1], a[mt], b1);
        }
}

template<bool H16_OUT>
__global__ void __launch_bounds__(256)
gemm_pre(const __nv_bfloat16* __restrict__ A,
         const __nv_bfloat16* __restrict__ W,
         const float* __restrict__ bias,
         float* __restrict__ Cf,
         __nv_bfloat16* __restrict__ Ch,
         int M, int N, int K, int qcols, float qscale)
{
    extern __shared__ __align__(128) char smem[];
    const uint32_t sb = smem_u32(smem);
    const int tid = threadIdx.x;
    const int lane = tid & 31, wid = tid >> 5;
    const int wm = wid >> 1, wn = wid & 1;
    const int m0 = blockIdx.y * 128;
    const int n0 = blockIdx.x * 128;

    float acc[2][8][4] = {};

    const int frow = lane & 15;
    const int fcol = ((lane >> 4) & 1) * 16;
    uint32_t a_addr[2], b_addr[4];
    #pragma unroll
    for (int mt = 0; mt < 2; mt++)
        a_addr[mt] = (uint32_t)((wm * 32 + mt * 16 + frow) * ROWB + fcol);
    #pragma unroll
    for (int p = 0; p < 4; p++)
        b_addr[p] = (uint32_t)((wn * 64 + p * 16 + frow) * ROWB + fcol);

    auto issue = [&](int stage, int k0) {
        const uint32_t sbuf = sb + stage * BUF_B;
        #pragma unroll
        for (int j = 0; j < 2; j++) {
            int cid = tid + j * 256;
            int r = cid >> 2, c16 = cid & 3;
            uint32_t so = (uint32_t)(r * ROWB + c16 * 16);
            size_t ga = (size_t)(m0 + r) * K + k0 + c16 * 8;
            size_t gb = (size_t)(n0 + r) * K + k0 + c16 * 8;
            CP16(sbuf + P_A + so, A + ga);
            CP16(sbuf + P_W + so, W + gb);
        }
        CP_COMMIT();
    };

    const int nch = K / 32;
    issue(0, 0);

    for (int i = 0; i < nch; i++) {
        CP_WAIT0();
        __syncthreads();
        const uint32_t base = sb + (i & 1) * BUF_B;

        uint32_t a0[2][4], b0[4][4], a1[2][4], b1[4][4];

        #pragma unroll
        for (int mt = 0; mt < 2; mt++)
            ldm_x4(a0[mt], base + P_A + a_addr[mt]);
        #pragma unroll
        for (int p = 0; p < 4; p++)
            ldm_x4(b0[p], base + P_W + b_addr[p]);

        if (i + 1 < nch) issue((i + 1) & 1, (i + 1) * 32);

        #pragma unroll
        for (int mt = 0; mt < 2; mt++)
            ldm_x4(a1[mt], base + P_A + a_addr[mt] + 32);
        #pragma unroll
        for (int p = 0; p < 4; p++)
            ldm_x4(b1[p], base + P_W + b_addr[p] + 32);

        mma_block_h(acc, a0, b0);      // kh=0
        mma_block_h(acc, a1, b1);      // kh=1
    }

    // epilogue
    const int g = lane >> 2, t = lane & 3;
    #pragma unroll
    for (int mt = 0; mt < 2; mt++) {
        int row = m0 + wm * 32 + mt * 16 + g;
        #pragma unroll
        for (int nt = 0; nt < 8; nt++) {
            int col = n0 + wn * 64 + nt * 8 + t * 2;
            float bx = bias[col], by = bias[col + 1];
            float* c = acc[mt][nt];
            float v0 = c[0] + bx, v1 = c[1] + by;
            float v2 = c[2] + bx, v3 = c[3] + by;
            if (H16_OUT) {
                float s = (col < qcols) ? qscale : 1.0f;
                *(uint32_t*)&Ch[(size_t)row * N + col]       = pack_h2(v0 * s, v1 * s);
                *(uint32_t*)&Ch[(size_t)(row + 8) * N + col] = pack_h2(v2 * s, v3 * s);
            } else {
                *(float2*)(Cf + (size_t)row * N + col) = make_float2(v0, v1);
                *(float2*)(Cf + (size_t)(row + 8) * N + col) = make_float2(v2, v3);
            }
        }
    }
}

// ===== fp16 flash attention: 1-term S (f32 acc), PV in fp16-D chains =======
#define KSTR 144
#define KV_PL   (64 * KSTR)                  // 9216 per plane
#define KV_B    (2 * KV_PL)                  // 18432 per stage (K, V)
#define AQ      0
#define AKV     (128 * KSTR)                 // 18432
#define ATT_SMEM (AKV + 2 * KV_B)            // 55296

__global__ void __launch_bounds__(256, 2)
attn_pre(const __nv_bfloat16* __restrict__ qkv,
         __nv_bfloat16* __restrict__ att)
{
    extern __shared__ __align__(128) char smem[];
    const uint32_t sb = smem_u32(smem);
    const int tid = threadIdx.x;
    const int lane = tid & 31, wid = tid >> 5;
    const int b = blockIdx.y >> 4, h = blockIdx.y & 15;
    const int q0 = blockIdx.x * 128;

    const size_t rs = 3 * EMB;
    const __nv_bfloat16* Qg = qkv + (size_t)(b * SEQ) * rs + h * HD;
    const __nv_bfloat16* Kg = Qg + EMB;
    const __nv_bfloat16* Vg = Qg + 2 * EMB;

    auto issueKV = [&](int stage, int k0) {
        const uint32_t sbuf = sb + AKV + stage * KV_B;
        #pragma unroll
        for (int i = 0; i < 2; i++) {
            int idx = tid + i * 256;           // 0..511
            int r = idx >> 3, c16 = idx & 7;
            size_t go = (size_t)(k0 + r) * rs + c16 * 8;
            uint32_t so = (uint32_t)(r * KSTR + c16 * 16);
            CP16(sbuf + 0 * KV_PL + so, Kg + go);
            CP16(sbuf + 1 * KV_PL + so, Vg + go);
        }
        CP_COMMIT();
    };

    issueKV(0, 0);

    // ---- load Q tile (sync; once) ----
    #pragma unroll
    for (int i = 0; i < 4; i++) {
        int idx = tid + i * 256;
        int r = idx >> 3, c16 = idx & 7;
        size_t go = (size_t)(q0 + r) * rs + c16 * 8;
        uint32_t so = r * KSTR + c16 * 16;
        *(uint4*)(smem + AQ + so) = *(const uint4*)(Qg + go);
    }

    const int frow = lane & 15;
    const int fcol = ((lane >> 4) & 1) * 16;
    const uint32_t qa = sb + AQ + (uint32_t)((wid * 16 + frow) * KSTR + fcol);
    const uint32_t kvf = (uint32_t)(frow * KSTR + fcol);

    float oacc[8][4] = {};
    float m0 = -1e30f, m1 = -1e30f;
    float l0 = 0.0f, l1 = 0.0f;

    for (int kt = 0; kt < SEQ / 64; kt++) {
        CP_WAIT0();
        __syncthreads();
        if (kt + 1 < SEQ / 64) issueKV((kt + 1) & 1, (kt + 1) * 64);

        const uint32_t base = sb + AKV + (kt & 1) * KV_B;
        const uint32_t ka = base + 0 * KV_PL + kvf;
        const uint32_t va = base + 1 * KV_PL + kvf;

        // ---- S = Q16 @ K16^T (16 x 64 per warp, 1-term, f32 accum) ----
        float sacc[8][4] = {};
        #pragma unroll
        for (int kk = 0; kk < 4; kk++) {
            uint32_t aq[4], kf[4][4];
            ldm_x4(aq, qa + kk * 32);
            #pragma unroll
            for (int p = 0; p < 4; p++)
                ldm_x4(kf[p], ka + p * (16 * KSTR) + kk * 32);
            #pragma unroll
            for (int p = 0; p < 4; p++) {
                uint32_t b0[2] = { kf[p][0], kf[p][2] };
                uint32_t b1[2] = { kf[p][1], kf[p][3] };
                mma16816h(sacc[2*p+0], aq, b0);
                mma16816h(sacc[2*p+1], aq, b1);
            }
        }

        // ---- online softmax (base-2, warp-local) ----
        float mx0 = -1e30f, mx1 = -1e30f;
        #pragma unroll
        for (int nt = 0; nt < 8; nt++) {
            mx0 = fmaxf(mx0, fmaxf(sacc[nt][0], sacc[nt][1]));
            mx1 = fmaxf(mx1, fmaxf(sacc[nt][2], sacc[nt][3]));
        }
        mx0 = fmaxf(mx0, __shfl_xor_sync(0xffffffffu, mx0, 1));
        mx0 = fmaxf(mx0, __shfl_xor_sync(0xffffffffu, mx0, 2));
        mx1 = fmaxf(mx1, __shfl_xor_sync(0xffffffffu, mx1, 1));
        mx1 = fmaxf(mx1, __shfl_xor_sync(0xffffffffu, mx1, 2));
        float mn0 = fmaxf(m0, mx0), mn1 = fmaxf(m1, mx1);
        float a0 = exp2f(m0 - mn0), a1 = exp2f(m1 - mn1);
        m0 = mn0; m1 = mn1;

        float ls0 = 0.0f, ls1 = 0.0f;
        #pragma unroll
        for (int nt = 0; nt < 8; nt++) {
            sacc[nt][0] = exp2f(sacc[nt][0] - mn0);
            sacc[nt][1] = exp2f(sacc[nt][1] - mn0);
            sacc[nt][2] = exp2f(sacc[nt][2] - mn1);
            sacc[nt][3] = exp2f(sacc[nt][3] - mn1);
            ls0 += sacc[nt][0] + sacc[nt][1];
            ls1 += sacc[nt][2] + sacc[nt][3];
        }
        l0 = l0 * a0 + ls0;
        l1 = l1 * a1 + ls1;

        // ---- PV: fp16-D chains of 2 MMAs (32 keys), spill to fp32 ----
        #pragma unroll
        for (int half = 0; half < 2; half++) {
            uint32_t od[8][2];
            #pragma unroll
            for (int nt = 0; nt < 8; nt++) { od[nt][0] = 0u; od[nt][1] = 0u; }

            #pragma unroll
            for (int kx = 0; kx < 2; kx++) {
                const int kk = half * 2 + kx;
                uint32_t ph[4], vf[4][4];
                ph[0] = pack_h2(sacc[2*kk  ][0], sacc[2*kk  ][1]);
                ph[1] = pack_h2(sacc[2*kk  ][2], sacc[2*kk  ][3]);
                ph[2] = pack_h2(sacc[2*kk+1][0], sacc[2*kk+1][1]);
                ph[3] = pack_h2(sacc[2*kk+1][2], sacc[2*kk+1][3]);
                #pragma unroll
                for (int nd = 0; nd < 4; nd++)
                    ldm_x4_t(vf[nd], va + kk * (16 * KSTR) + nd * 32);
                #pragma unroll
                for (int nd = 0; nd < 4; nd++) {
                    uint32_t b0[2] = { vf[nd][0], vf[nd][1] };
                    uint32_t b1[2] = { vf[nd][2], vf[nd][3] };
                    mma16816hh(od[2*nd+0], ph, b0);
                    mma16816hh(od[2*nd+1], ph, b1);
                }
            }

            // spill: first half does the rescale-merge, second half plain add
            #pragma unroll
            for (int nt = 0; nt < 8; nt++) {
                float2 lo = __half22float2(*(__half2*)&od[nt][0]);
                float2 hi = __half22float2(*(__half2*)&od[nt][1]);
                if (half == 0) {
                    oacc[nt][0] = fmaf(oacc[nt][0], a0, lo.x);
                    oacc[nt][1] = fmaf(oacc[nt][1], a0, lo.y);
                    oacc[nt][2] = fmaf(oacc[nt][2], a1, hi.x);
                    oacc[nt][3] = fmaf(oacc[nt][3], a1, hi.y);
                } else {
                    oacc[nt][0] += lo.x;
                    oacc[nt][1] += lo.y;
                    oacc[nt][2] += hi.x;
                    oacc[nt][3] += hi.y;
                }
            }
        }
    }

    // ---- finalize: normalize, fp16 store ----
    l0 += __shfl_xor_sync(0xffffffffu, l0, 1);
    l0 += __shfl_xor_sync(0xffffffffu, l0, 2);
    l1 += __shfl_xor_sync(0xffffffffu, l1, 1);
    l1 += __shfl_xor_sync(0xffffffffu, l1, 2);
    float inv0 = 1.0f / l0, inv1 = 1.0f / l1;

    const int g = lane >> 2, t = lane & 3;
    const int row = q0 + wid * 16 + g;
    size_t o0 = (size_t)(b * SEQ + row) * EMB + h * HD;
    size_t o1 = (size_t)(b * SEQ + row + 8) * EMB + h * HD;
    #pragma unroll
    for (int nt = 0; nt < 8; nt++) {
        int col = nt * 8 + t * 2;
        *(uint32_t*)&att[o0 + col] = pack_h2(oacc[nt][0] * inv0, oacc[nt][1] * inv0);
        *(uint32_t*)&att[o1 + col] = pack_h2(oacc[nt][2] * inv1, oacc[nt][3] * inv1);
    }
}

// ---------------------------------------------------------------------------
extern "C" void kernel_launch(void* const* d_in, const int* in_sizes, int n_in,
                              void* d_out, int out_size)
{
    const float* x      = (const float*)d_in[0];
    const float* w_qkv  = (const float*)d_in[1];
    const float* b_qkv  = (const float*)d_in[2];
    const float* w_proj = (const float*)d_in[3];
    const float* b_proj = (const float*)d_in[4];
    float* out = (float*)d_out;

    __nv_bfloat16 *x16, *wq, *wp, *qkv, *att;
    cudaGetSymbolAddress((void**)&x16, g_x16);
    cudaGetSymbolAddress((void**)&wq, g_wq);
    cudaGetSymbolAddress((void**)&wp, g_wp);
    cudaGetSymbolAddress((void**)&qkv, g_qkv);
    cudaGetSymbolAddress((void**)&att, g_att);

    cudaFuncSetAttribute((const void*)gemm_pre<true>,
                         cudaFuncAttributeMaxDynamicSharedMemorySize, GEMM_SMEM);
    cudaFuncSetAttribute((const void*)gemm_pre<false>,
                         cudaFuncAttributeMaxDynamicSharedMemorySize, GEMM_SMEM);
    cudaFuncSetAttribute(attn_pre, cudaFuncAttributeMaxDynamicSharedMemorySize, ATT_SMEM);

    // 0) pre-convert operands to fp16
    {
        int n4 = TOK * EMB / 4;
        cvt_f32h<<<(n4 + 255) / 256, 256>>>(x, x16, n4);
        n4 = 3 * EMB * EMB / 4;
        cvt_f32h<<<(n4 + 255) / 256, 256>>>(w_qkv, wq, n4);
        n4 = EMB * EMB / 4;
        cvt_f32h<<<(n4 + 255) / 256, 256>>>(w_proj, wp, n4);
    }

    const float QSCALE = 0.125f * 1.4426950408889634f;   // 1/sqrt(64) * log2(e)

    // 1) QKV projection (1-term fp16) -> fp16 qkv (Q cols pre-scaled)
    dim3 g1(3 * EMB / 128, TOK / 128);
    gemm_pre<true><<<g1, 256, GEMM_SMEM>>>(x16, wq, b_qkv,
                                           nullptr, qkv,
                                           TOK, 3 * EMB, EMB, EMB, QSCALE);

    // 2) Attention (f32-acc S, fp16-D PV) -> fp16 att
    dim3 g2(SEQ / 128, BATCH * NH);
    attn_pre<<<g2, 256, ATT_SMEM>>>(qkv, att);

    // 3) Output projection (1-term fp16) -> fp32 out
    dim3 g3(EMB / 128, TOK / 128);
    gemm_pre<false><<<g3, 256, GEMM_SMEM>>>(att, wp, b_proj,
                                            out, nullptr,
                                            TOK, EMB, EMB, 0, 1.0f);
}

// round 17
// speedup vs baseline: 1.0716x; 1.0716x over previous
#include <cuda_runtime.h>
#include <cuda_bf16.h>
#include <cuda_fp16.h>
#include <cstdint>

#define BATCH 4
#define SEQ   2048
#define EMB   1024
#define NH    16
#define HD    64
#define TOK   (BATCH*SEQ)      // 8192

// ---------------- scratch (device globals; single fp16 everywhere) ---------
__device__ __nv_bfloat16 g_x16[(size_t)TOK * EMB];        // fp16
__device__ __nv_bfloat16 g_wq[(size_t)3 * EMB * EMB];     // fp16
__device__ __nv_bfloat16 g_wp[(size_t)EMB * EMB];         // fp16
__device__ __nv_bfloat16 g_qkv[(size_t)TOK * 3 * EMB];    // fp16 (Q scaled)
__device__ __nv_bfloat16 g_att[(size_t)TOK * EMB];        // fp16

// ---------------- primitives ----------------
__device__ __forceinline__ uint32_t smem_u32(const void* p) {
    uint32_t a;
    asm("{ .reg .u64 t; cvta.to.shared.u64 t, %1; cvt.u32.u64 %0, t; }" : "=r"(a) : "l"(p));
    return a;
}
__device__ __forceinline__ void ldm_x4(uint32_t* r, uint32_t addr) {
    asm volatile("ldmatrix.sync.aligned.m8n8.x4.shared.b16 {%0,%1,%2,%3}, [%4];"
        : "=r"(r[0]), "=r"(r[1]), "=r"(r[2]), "=r"(r[3]) : "r"(addr));
}
__device__ __forceinline__ void ldm_x4_t(uint32_t* r, uint32_t addr) {
    asm volatile("ldmatrix.sync.aligned.m8n8.x4.trans.shared.b16 {%0,%1,%2,%3}, [%4];"
        : "=r"(r[0]), "=r"(r[1]), "=r"(r[2]), "=r"(r[3]) : "r"(addr));
}
__device__ __forceinline__ void mma16816h(float* c, const uint32_t* a, const uint32_t* b) {
    asm volatile(
        "mma.sync.aligned.m16n8k16.row.col.f32.f16.f16.f32 "
        "{%0,%1,%2,%3}, {%4,%5,%6,%7}, {%8,%9}, {%0,%1,%2,%3};"
        : "+f"(c[0]), "+f"(c[1]), "+f"(c[2]), "+f"(c[3])
        : "r"(a[0]), "r"(a[1]), "r"(a[2]), "r"(a[3]), "r"(b[0]), "r"(b[1]));
}
#define CP16(dst, src) \
    asm volatile("cp.async.cg.shared.global [%0], [%1], 16;" \
        :: "r"(dst), "l"(src) : "memory")
#define CP_COMMIT() asm volatile("cp.async.commit_group;" ::: "memory")
#define CP_WAIT0()  asm volatile("cp.async.wait_group 0;" ::: "memory")

__device__ __forceinline__ uint32_t pack_h2(float x, float y) {
    __half2 h = __floats2half2_rn(x, y);
    return *(uint32_t*)&h;
}

// ---------------- conversion kernel (fp32 -> fp16) ----------------
__global__ void __launch_bounds__(256)
cvt_f32h(const float* __restrict__ in, __nv_bfloat16* __restrict__ h, int n4)
{
    int i = blockIdx.x * blockDim.x + threadIdx.x;
    if (i < n4) {
        float4 v = ((const float4*)in)[i];
        uint2 hi;
        hi.x = pack_h2(v.x, v.y);
        hi.y = pack_h2(v.z, v.w);
        ((uint2*)h)[i] = hi;
    }
}

// ======== fp16 1-term GEMM, BK=64 (16 barriers for K=1024) ========
#define ROWB    144                // 128B data + 16B pad (conflict-free)
#define PLANE_B (128 * ROWB)       // 18432
#define P_A     0
#define P_W     (1 * PLANE_B)
#define BUF_B   (2 * PLANE_B)      // 36864
#define GEMM_SMEM (2 * BUF_B)      // 73728 -> 2 CTAs/SM

__device__ __forceinline__ void mma_block_h(float acc[2][8][4],
        const uint32_t a[2][4], const uint32_t b[4][4]) {
    #pragma unroll
    for (int mt = 0; mt < 2; mt++)
        #pragma unroll
        for (int p = 0; p < 4; p++) {
            uint32_t b0[2] = { b[p][0], b[p][2] };
            uint32_t b1[2] = { b[p][1], b[p][3] };
            mma16816h(acc[mt][2*p+0], a[mt], b0);
            mma16816h(acc[mt][2*p+1], a[mt], b1);
        }
}

template<bool H16_OUT>
__global__ void __launch_bounds__(256)
gemm_pre(const __nv_bfloat16* __restrict__ A,
         const __nv_bfloat16* __restrict__ W,
         const float* __restrict__ bias,
         float* __restrict__ Cf,
         __nv_bfloat16* __restrict__ Ch,
         int M, int N, int K, int qcols, float qscale)
{
    extern __shared__ __align__(128) char smem[];
    const uint32_t sb = smem_u32(smem);
    const int tid = threadIdx.x;
    const int lane = tid & 31, wid = tid >> 5;
    const int wm = wid >> 1, wn = wid & 1;
    const int m0 = blockIdx.y * 128;
    const int n0 = blockIdx.x * 128;

    float acc[2][8][4] = {};

    const int frow = lane & 15;
    const int fcol = ((lane >> 4) & 1) * 16;
    uint32_t a_addr[2], b_addr[4];
    #pragma unroll
    for (int mt = 0; mt < 2; mt++)
        a_addr[mt] = (uint32_t)((wm * 32 + mt * 16 + frow) * ROWB + fcol);
    #pragma unroll
    for (int p = 0; p < 4; p++)
        b_addr[p] = (uint32_t)((wn * 64 + p * 16 + frow) * ROWB + fcol);

    auto issue = [&](int stage, int k0) {
        const uint32_t sbuf = sb + stage * BUF_B;
        #pragma unroll
        for (int j = 0; j < 4; j++) {
            int cid = tid + j * 256;           // 0..1023
            int r = cid >> 3, c16 = cid & 7;
            uint32_t so = (uint32_t)(r * ROWB + c16 * 16);
            CP16(sbuf + P_A + so, A + (size_t)(m0 + r) * K + k0 + c16 * 8);
            CP16(sbuf + P_W + so, W + (size_t)(n0 + r) * K + k0 + c16 * 8);
        }
        CP_COMMIT();
    };

    const int nch = K / 64;
    issue(0, 0);

    for (int i = 0; i < nch; i++) {
        CP_WAIT0();
        __syncthreads();
        const uint32_t base = sb + (i & 1) * BUF_B;

        uint32_t a0[2][4], b0[4][4], a1[2][4], b1[4][4];

        // fragments kh=0
        #pragma unroll
        for (int mt = 0; mt < 2; mt++)
            ldm_x4(a0[mt], base + P_A + a_addr[mt]);
        #pragma unroll
        for (int p = 0; p < 4; p++)
            ldm_x4(b0[p], base + P_W + b_addr[p]);

        if (i + 1 < nch) issue((i + 1) & 1, (i + 1) * 64);

        // kh=1 prefetched under kh=0 MMAs, etc.
        #pragma unroll
        for (int mt = 0; mt < 2; mt++)
            ldm_x4(a1[mt], base + P_A + a_addr[mt] + 32);
        #pragma unroll
        for (int p = 0; p < 4; p++)
            ldm_x4(b1[p], base + P_W + b_addr[p] + 32);

        mma_block_h(acc, a0, b0);      // kh=0

        #pragma unroll
        for (int mt = 0; mt < 2; mt++)
            ldm_x4(a0[mt], base + P_A + a_addr[mt] + 64);
        #pragma unroll
        for (int p = 0; p < 4; p++)
            ldm_x4(b0[p], base + P_W + b_addr[p] + 64);

        mma_block_h(acc, a1, b1);      // kh=1

        #pragma unroll
        for (int mt = 0; mt < 2; mt++)
            ldm_x4(a1[mt], base + P_A + a_addr[mt] + 96);
        #pragma unroll
        for (int p = 0; p < 4; p++)
            ldm_x4(b1[p], base + P_W + b_addr[p] + 96);

        mma_block_h(acc, a0, b0);      // kh=2
        mma_block_h(acc, a1, b1);      // kh=3
    }

    // epilogue
    const int g = lane >> 2, t = lane & 3;
    #pragma unroll
    for (int mt = 0; mt < 2; mt++) {
        int row = m0 + wm * 32 + mt * 16 + g;
        #pragma unroll
        for (int nt = 0; nt < 8; nt++) {
            int col = n0 + wn * 64 + nt * 8 + t * 2;
            float bx = bias[col], by = bias[col + 1];
            float* c = acc[mt][nt];
            float v0 = c[0] + bx, v1 = c[1] + by;
            float v2 = c[2] + bx, v3 = c[3] + by;
            if (H16_OUT) {
                float s = (col < qcols) ? qscale : 1.0f;
                *(uint32_t*)&Ch[(size_t)row * N + col]       = pack_h2(v0 * s, v1 * s);
                *(uint32_t*)&Ch[(size_t)(row + 8) * N + col] = pack_h2(v2 * s, v3 * s);
            } else {
                *(float2*)(Cf + (size_t)row * N + col) = make_float2(v0, v1);
                *(float2*)(Cf + (size_t)(row + 8) * N + col) = make_float2(v2, v3);
            }
        }
    }
}

// ===== fp16 flash attention: round-15 math, 128-key stages (16 barriers) ====
#define KSTR 144
#define KV_PL   (128 * KSTR)                 // 18432 per plane per stage
#define KV_B    (2 * KV_PL)                  // 36864 per stage (K, V)
#define AQ      0
#define AKV     (128 * KSTR)                 // 18432
#define ATT_SMEM (AKV + 2 * KV_B)            // 92160 -> 2 CTAs/SM

__global__ void __launch_bounds__(256, 2)
attn_pre(const __nv_bfloat16* __restrict__ qkv,
         __nv_bfloat16* __restrict__ att)
{
    extern __shared__ __align__(128) char smem[];
    const uint32_t sb = smem_u32(smem);
    const int tid = threadIdx.x;
    const int lane = tid & 31, wid = tid >> 5;
    const int b = blockIdx.y >> 4, h = blockIdx.y & 15;
    const int q0 = blockIdx.x * 128;

    const size_t rs = 3 * EMB;
    const __nv_bfloat16* Qg = qkv + (size_t)(b * SEQ) * rs + h * HD;
    const __nv_bfloat16* Kg = Qg + EMB;
    const __nv_bfloat16* Vg = Qg + 2 * EMB;

    auto issueKV = [&](int stage, int k0) {
        const uint32_t sbuf = sb + AKV + stage * KV_B;
        #pragma unroll
        for (int i = 0; i < 4; i++) {
            int idx = tid + i * 256;           // 0..1023
            int r = idx >> 3, c16 = idx & 7;
            size_t go = (size_t)(k0 + r) * rs + c16 * 8;
            uint32_t so = (uint32_t)(r * KSTR + c16 * 16);
            CP16(sbuf + 0 * KV_PL + so, Kg + go);
            CP16(sbuf + 1 * KV_PL + so, Vg + go);
        }
        CP_COMMIT();
    };

    issueKV(0, 0);

    // ---- load Q tile (sync; once) ----
    #pragma unroll
    for (int i = 0; i < 4; i++) {
        int idx = tid + i * 256;
        int r = idx >> 3, c16 = idx & 7;
        size_t go = (size_t)(q0 + r) * rs + c16 * 8;
        uint32_t so = r * KSTR + c16 * 16;
        *(uint4*)(smem + AQ + so) = *(const uint4*)(Qg + go);
    }

    const int frow = lane & 15;
    const int fcol = ((lane >> 4) & 1) * 16;
    const uint32_t qa = sb + AQ + (uint32_t)((wid * 16 + frow) * KSTR + fcol);
    const uint32_t kvf = (uint32_t)(frow * KSTR + fcol);

    float oacc[8][4] = {};
    float m0 = -1e30f, m1 = -1e30f;
    float l0 = 0.0f, l1 = 0.0f;

    for (int kt = 0; kt < SEQ / 128; kt++) {
        CP_WAIT0();
        __syncthreads();
        if (kt + 1 < SEQ / 128) issueKV((kt + 1) & 1, (kt + 1) * 128);

        const uint32_t stg = sb + AKV + (kt & 1) * KV_B;

        #pragma unroll
        for (int half = 0; half < 2; half++) {
            const uint32_t ka = stg + 0 * KV_PL + half * (64 * KSTR) + kvf;
            const uint32_t va = stg + 1 * KV_PL + half * (64 * KSTR) + kvf;

            // ---- S = Q16 @ K16^T (16 x 64 per warp, 1-term) ----
            float sacc[8][4] = {};
            #pragma unroll
            for (int kk = 0; kk < 4; kk++) {
                uint32_t aq[4], kf[4][4];
                ldm_x4(aq, qa + kk * 32);
                #pragma unroll
                for (int p = 0; p < 4; p++)
                    ldm_x4(kf[p], ka + p * (16 * KSTR) + kk * 32);
                #pragma unroll
                for (int p = 0; p < 4; p++) {
                    uint32_t b0[2] = { kf[p][0], kf[p][2] };
                    uint32_t b1[2] = { kf[p][1], kf[p][3] };
                    mma16816h(sacc[2*p+0], aq, b0);
                    mma16816h(sacc[2*p+1], aq, b1);
                }
            }

            // ---- online softmax (base-2, warp-local) ----
            float mx0 = -1e30f, mx1 = -1e30f;
            #pragma unroll
            for (int nt = 0; nt < 8; nt++) {
                mx0 = fmaxf(mx0, fmaxf(sacc[nt][0], sacc[nt][1]));
                mx1 = fmaxf(mx1, fmaxf(sacc[nt][2], sacc[nt][3]));
            }
            mx0 = fmaxf(mx0, __shfl_xor_sync(0xffffffffu, mx0, 1));
            mx0 = fmaxf(mx0, __shfl_xor_sync(0xffffffffu, mx0, 2));
            mx1 = fmaxf(mx1, __shfl_xor_sync(0xffffffffu, mx1, 1));
            mx1 = fmaxf(mx1, __shfl_xor_sync(0xffffffffu, mx1, 2));
            float mn0 = fmaxf(m0, mx0), mn1 = fmaxf(m1, mx1);
            float a0 = exp2f(m0 - mn0), a1 = exp2f(m1 - mn1);
            m0 = mn0; m1 = mn1;

            float ls0 = 0.0f, ls1 = 0.0f;
            #pragma unroll
            for (int nt = 0; nt < 8; nt++) {
                sacc[nt][0] = exp2f(sacc[nt][0] - mn0);
                sacc[nt][1] = exp2f(sacc[nt][1] - mn0);
                sacc[nt][2] = exp2f(sacc[nt][2] - mn1);
                sacc[nt][3] = exp2f(sacc[nt][3] - mn1);
                ls0 += sacc[nt][0] + sacc[nt][1];
                ls1 += sacc[nt][2] + sacc[nt][3];
            }
            l0 = l0 * a0 + ls0;
            l1 = l1 * a1 + ls1;
            #pragma unroll
            for (int nt = 0; nt < 8; nt++) {
                oacc[nt][0] *= a0; oacc[nt][1] *= a0;
                oacc[nt][2] *= a1; oacc[nt][3] *= a1;
            }

            // ---- O += P16 @ V16 (1-term, f32 accum) ----
            #pragma unroll
            for (int kk = 0; kk < 4; kk++) {
                uint32_t ph[4], vf[4][4];
                ph[0] = pack_h2(sacc[2*kk  ][0], sacc[2*kk  ][1]);
                ph[1] = pack_h2(sacc[2*kk  ][2], sacc[2*kk  ][3]);
                ph[2] = pack_h2(sacc[2*kk+1][0], sacc[2*kk+1][1]);
                ph[3] = pack_h2(sacc[2*kk+1][2], sacc[2*kk+1][3]);
                #pragma unroll
                for (int nd = 0; nd < 4; nd++)
                    ldm_x4_t(vf[nd], va + kk * (16 * KSTR) + nd * 32);
                #pragma unroll
                for (int nd = 0; nd < 4; nd++) {
                    uint32_t b0[2] = { vf[nd][0], vf[nd][1] };
                    uint32_t b1[2] = { vf[nd][2], vf[nd][3] };
                    mma16816h(oacc[2*nd+0], ph, b0);
                    mma16816h(oacc[2*nd+1], ph, b1);
                }
            }
        }
    }

    // ---- finalize: normalize, fp16 store ----
    l0 += __shfl_xor_sync(0xffffffffu, l0, 1);
    l0 += __shfl_xor_sync(0xffffffffu, l0, 2);
    l1 += __shfl_xor_sync(0xffffffffu, l1, 1);
    l1 += __shfl_xor_sync(0xffffffffu, l1, 2);
    float inv0 = 1.0f / l0, inv1 = 1.0f / l1;

    const int g = lane >> 2, t = lane & 3;
    const int row = q0 + wid * 16 + g;
    size_t o0 = (size_t)(b * SEQ + row) * EMB + h * HD;
    size_t o1 = (size_t)(b * SEQ + row + 8) * EMB + h * HD;
    #pragma unroll
    for (int nt = 0; nt < 8; nt++) {
        int col = nt * 8 + t * 2;
        *(uint32_t*)&att[o0 + col] = pack_h2(oacc[nt][0] * inv0, oacc[nt][1] * inv0);
        *(uint32_t*)&att[o1 + col] = pack_h2(oacc[nt][2] * inv1, oacc[nt][3] * inv1);
    }
}

// ---------------------------------------------------------------------------
extern "C" void kernel_launch(void* const* d_in, const int* in_sizes, int n_in,
                              void* d_out, int out_size)
{
    const float* x      = (const float*)d_in[0];
    const float* w_qkv  = (const float*)d_in[1];
    const float* b_qkv  = (const float*)d_in[2];
    const float* w_proj = (const float*)d_in[3];
    const float* b_proj = (const float*)d_in[4];
    float* out = (float*)d_out;

    __nv_bfloat16 *x16, *wq, *wp, *qkv, *att;
    cudaGetSymbolAddress((void**)&x16, g_x16);
    cudaGetSymbolAddress((void**)&wq, g_wq);
    cudaGetSymbolAddress((void**)&wp, g_wp);
    cudaGetSymbolAddress((void**)&qkv, g_qkv);
    cudaGetSymbolAddress((void**)&att, g_att);

    cudaFuncSetAttribute((const void*)gemm_pre<true>,
                         cudaFuncAttributeMaxDynamicSharedMemorySize, GEMM_SMEM);
    cudaFuncSetAttribute((const void*)gemm_pre<false>,
                         cudaFuncAttributeMaxDynamicSharedMemorySize, GEMM_SMEM);
    cudaFuncSetAttribute(attn_pre, cudaFuncAttributeMaxDynamicSharedMemorySize, ATT_SMEM);

    // 0) pre-convert operands to fp16
    {
        int n4 = TOK * EMB / 4;
        cvt_f32h<<<(n4 + 255) / 256, 256>>>(x, x16, n4);
        n4 = 3 * EMB * EMB / 4;
        cvt_f32h<<<(n4 + 255) / 256, 256>>>(w_qkv, wq, n4);
        n4 = EMB * EMB / 4;
        cvt_f32h<<<(n4 + 255) / 256, 256>>>(w_proj, wp, n4);
    }

    const float QSCALE = 0.125f * 1.4426950408889634f;   // 1/sqrt(64) * log2(e)

    // 1) QKV projection (1-term fp16, BK=64) -> fp16 qkv (Q cols pre-scaled)
    dim3 g1(3 * EMB / 128, TOK / 128);
    gemm_pre<true><<<g1, 256, GEMM_SMEM>>>(x16, wq, b_qkv,
                                           nullptr, qkv,
                                           TOK, 3 * EMB, EMB, EMB, QSCALE);

    // 2) Attention (1-term S + 1-term PV, 128-key stages) -> fp16 att
    dim3 g2(SEQ / 128, BATCH * NH);
    attn_pre<<<g2, 256, ATT_SMEM>>>(qkv, att);

    // 3) Output projection (1-term fp16, BK=64) -> fp32 out
    dim3 g3(EMB / 128, TOK / 128);
    gemm_pre<false><<<g3, 256, GEMM_SMEM>>>(att, wp, b_proj,
                                            out, nullptr,
                                            TOK, EMB, EMB, 0, 1.0f);
}